// round 1
// baseline (speedup 1.0000x reference)
#include <cuda_runtime.h>
#include <math.h>
#include <float.h>

// Problem constants
#define N_TOK   2048        // B*T = 2*1024
#define C_IN    1024        // d_in
#define HEADS_N 4
#define KDIM    512
#define HALF_D  256
#define NKEYS   512
#define KNN_K   32
#define VDIM    512
#define DOUT    1024

// ---------------- scratch (static device, no allocation) ----------------
__device__ float g_q[(size_t)N_TOK * 2048];           // 16 MB
__device__ float g_scores[(size_t)N_TOK * 4096];      // 32 MB  (n, ht=h*2+t, 512)
__device__ float g_ts[(size_t)N_TOK * 8 * KNN_K];     // stage-1 topk vals
__device__ int   g_ti[(size_t)N_TOK * 8 * KNN_K];     // stage-1 topk idx
__device__ float g_cw[(size_t)N_TOK * HEADS_N * KNN_K]; // softmax weights
__device__ int   g_ci[(size_t)N_TOK * HEADS_N * KNN_K]; // combined value idx
__device__ float g_gate[(size_t)N_TOK * VDIM];        // silu(x@Ws+bs)
__device__ float g_hidden[(size_t)N_TOK * VDIM];      // gate * v_out

// ---------------- generic fp32 GEMM: C = A @ B (+bias, act) ----------------
// BT=true  -> C = A @ B^T  (B row-major N x K)
// ACT: 0 = none, 1 = silu
// batching via blockIdx.z with element offsets sA/sB/sC
template<bool BT, int ACT>
__global__ __launch_bounds__(256) void gemm_k(
    const float* __restrict__ A, const float* __restrict__ B,
    const float* __restrict__ bias, float* __restrict__ C,
    int K, int lda, int ldb, int ldc,
    long sA, long sB, long sC)
{
    constexpr int BM = 128, BN = 64, BK = 16;
    __shared__ float As[BK][BM];
    __shared__ float Bs[BK][BN];

    A += (long)blockIdx.z * sA;
    B += (long)blockIdx.z * sB;
    C += (long)blockIdx.z * sC;

    const int bm = blockIdx.y * BM;
    const int bn = blockIdx.x * BN;
    const int tid = threadIdx.x;
    const int tx = tid & 15;   // col group -> 4 cols
    const int ty = tid >> 4;   // row group -> 8 rows

    float acc[8][4];
#pragma unroll
    for (int i = 0; i < 8; i++)
#pragma unroll
        for (int j = 0; j < 4; j++) acc[i][j] = 0.0f;

    for (int k0 = 0; k0 < K; k0 += BK) {
        // A tile: 128 rows x 16 k  (2048 floats, 2 float4 per thread), transpose to As[k][m]
#pragma unroll
        for (int it = 0; it < 2; it++) {
            int r = (tid >> 2) + it * 64;
            int c = (tid & 3) * 4;
            float4 a4 = *(const float4*)(A + (long)(bm + r) * lda + k0 + c);
            As[c + 0][r] = a4.x; As[c + 1][r] = a4.y;
            As[c + 2][r] = a4.z; As[c + 3][r] = a4.w;
        }
        if (BT) {
            // B is (N x K) row-major; tile 64 rows x 16 k, transpose to Bs[k][n]
            int r = tid >> 2;          // 0..63
            int c = (tid & 3) * 4;
            float4 b4 = *(const float4*)(B + (long)(bn + r) * ldb + k0 + c);
            Bs[c + 0][r] = b4.x; Bs[c + 1][r] = b4.y;
            Bs[c + 2][r] = b4.z; Bs[c + 3][r] = b4.w;
        } else {
            // B is (K x N) row-major; tile 16 k x 64 n
            int kk = tid >> 4;          // 0..15
            int c  = (tid & 15) * 4;
            *(float4*)&Bs[kk][c] = *(const float4*)(B + (long)(k0 + kk) * ldb + bn + c);
        }
        __syncthreads();

#pragma unroll
        for (int kk = 0; kk < BK; kk++) {
            float4 a0 = *(const float4*)&As[kk][ty * 8];
            float4 a1 = *(const float4*)&As[kk][ty * 8 + 4];
            float4 b  = *(const float4*)&Bs[kk][tx * 4];
            float av[8] = {a0.x, a0.y, a0.z, a0.w, a1.x, a1.y, a1.z, a1.w};
            float bv[4] = {b.x, b.y, b.z, b.w};
#pragma unroll
            for (int i = 0; i < 8; i++)
#pragma unroll
                for (int j = 0; j < 4; j++)
                    acc[i][j] += av[i] * bv[j];
        }
        __syncthreads();
    }

#pragma unroll
    for (int i = 0; i < 8; i++) {
        int r = bm + ty * 8 + i;
        float4 o;
        float* po = &o.x;
#pragma unroll
        for (int j = 0; j < 4; j++) {
            int c = bn + tx * 4 + j;
            float v = acc[i][j] + (bias ? bias[c] : 0.0f);
            if (ACT == 1) v = v / (1.0f + expf(-v));   // silu
            po[j] = v;
        }
        *(float4*)(C + (long)r * ldc + bn + tx * 4) = o;
    }
}

// ---------------- stage-1 top-32 of 512, per (n, ht) ----------------
// one warp per (n, ht); block = 8 warps = one token
__global__ __launch_bounds__(256) void topk1_kernel()
{
    int n = blockIdx.x;
    int w = threadIdx.x >> 5;       // ht = h*2+t
    int lane = threadIdx.x & 31;
    const float* sc = g_scores + (size_t)n * 4096 + (size_t)w * 512;

    __shared__ float sv[8][16][32];

    float lmax = -FLT_MAX; int lslot = 0;
#pragma unroll
    for (int i = 0; i < 16; i++) {
        float v = sc[i * 32 + lane];
        sv[w][i][lane] = v;
        if (v > lmax) { lmax = v; lslot = i; }
    }
    __syncwarp();

    float outV = 0.0f; int outI = 0;
    const unsigned FULL = 0xffffffffu;
    for (int it = 0; it < 32; it++) {
        float m = lmax;
        int mk = lslot * 32 + lane;   // global key index 0..511
#pragma unroll
        for (int off = 16; off; off >>= 1) {
            float om = __shfl_xor_sync(FULL, m, off);
            int   ok = __shfl_xor_sync(FULL, mk, off);
            if (om > m || (om == m && ok < mk)) { m = om; mk = ok; }
        }
        if (lane == it) { outV = m; outI = mk; }
        if (lane == (mk & 31)) {
            sv[w][mk >> 5][lane] = -FLT_MAX;
            lmax = -FLT_MAX; lslot = 0;
#pragma unroll
            for (int i = 0; i < 16; i++) {
                float v = sv[w][i][lane];
                if (v > lmax) { lmax = v; lslot = i; }
            }
        }
    }
    size_t o = ((size_t)n * 8 + w) * KNN_K + lane;
    g_ts[o] = outV;
    g_ti[o] = outI;
}

// ---------------- stage-2: all-pairs top-32 + softmax, per (n, h) ----------------
// one warp per (n, h); block = 4 warps = one token
__global__ __launch_bounds__(128) void topk2_kernel()
{
    int n = blockIdx.x;
    int h = threadIdx.x >> 5;
    int lane = threadIdx.x & 31;

    size_t base1 = ((size_t)n * 8 + h * 2) * KNN_K;   // half 0
    size_t base2 = base1 + KNN_K;                     // half 1

    __shared__ float s2s[4][32];
    __shared__ int   i1s[4][32];
    __shared__ int   i2s[4][32];

    float s1 = g_ts[base1 + lane];
    s2s[h][lane] = g_ts[base2 + lane];
    i1s[h][lane] = g_ti[base1 + lane];
    i2s[h][lane] = g_ti[base2 + lane];
    __syncwarp();

    unsigned alive = 0xffffffffu;
    float rmax = -FLT_MAX; int rj = 0;
    // initial row scan: row = lane (s1[lane] + s2[j])
    for (int j = 0; j < 32; j++) {
        float c = s1 + s2s[h][j];
        if (c > rmax) { rmax = c; rj = j; }
    }

    float outS = 0.0f; int outIdx = 0;
    const unsigned FULL = 0xffffffffu;
    for (int it = 0; it < 32; it++) {
        float m = rmax;
        int mk = lane * 32 + rj;     // flattened pair key 0..1023
#pragma unroll
        for (int off = 16; off; off >>= 1) {
            float om = __shfl_xor_sync(FULL, m, off);
            int   ok = __shfl_xor_sync(FULL, mk, off);
            if (om > m || (om == m && ok < mk)) { m = om; mk = ok; }
        }
        if (lane == it) {
            outS = m;
            outIdx = i1s[h][mk >> 5] * NKEYS + i2s[h][mk & 31];
        }
        if (lane == (mk >> 5)) {
            alive &= ~(1u << (mk & 31));
            rmax = -FLT_MAX; rj = 0;
            for (int j = 0; j < 32; j++) {
                if ((alive >> j) & 1u) {
                    float c = s1 + s2s[h][j];
                    if (c > rmax) { rmax = c; rj = j; }
                }
            }
        }
    }

    // softmax over the 32 extracted values (lane 0 holds the max: sorted order)
    float mx = __shfl_sync(FULL, outS, 0);
    float e = expf(outS - mx);
    float s = e;
#pragma unroll
    for (int off = 16; off; off >>= 1) s += __shfl_xor_sync(FULL, s, off);
    float wgt = e / s;

    size_t o = ((size_t)n * HEADS_N + h) * KNN_K + lane;
    g_cw[o] = wgt;
    g_ci[o] = outIdx;
}

// ---------------- gather: v_out = sum_k w_k * values[idx_k], * gate ----------------
// one block per token, 128 threads, float4 per thread (512 dims)
__global__ __launch_bounds__(128) void gather_kernel(const float* __restrict__ values)
{
    int n = blockIdx.x;
    int t = threadIdx.x;

    __shared__ float sw[128];
    __shared__ int   sid[128];
    sw[t]  = g_cw[(size_t)n * 128 + t];
    sid[t] = g_ci[(size_t)n * 128 + t];
    __syncthreads();

    float4 acc = {0.f, 0.f, 0.f, 0.f};
#pragma unroll 4
    for (int r = 0; r < 128; r++) {
        float wr = sw[r];
        const float4 v = *((const float4*)(values + (size_t)sid[r] * VDIM) + t);
        acc.x += wr * v.x; acc.y += wr * v.y;
        acc.z += wr * v.z; acc.w += wr * v.w;
    }

    float4 g = *(const float4*)(g_gate + (size_t)n * VDIM + t * 4);
    float4 out;
    out.x = acc.x * g.x; out.y = acc.y * g.y;
    out.z = acc.z * g.z; out.w = acc.w * g.w;
    *(float4*)(g_hidden + (size_t)n * VDIM + t * 4) = out;
}

// ---------------- launch ----------------
extern "C" void kernel_launch(void* const* d_in, const int* in_sizes, int n_in,
                              void* d_out, int out_size)
{
    const float* x      = (const float*)d_in[0];  // (2048, 1024)
    const float* Wq     = (const float*)d_in[1];  // (1024, 2048)
    const float* bq     = (const float*)d_in[2];  // (2048)
    const float* keys   = (const float*)d_in[3];  // (4096, 256)
    const float* values = (const float*)d_in[4];  // (262144, 512)
    const float* Ws     = (const float*)d_in[5];  // (1024, 512)
    const float* bs     = (const float*)d_in[6];  // (512)
    const float* Wv     = (const float*)d_in[7];  // (512, 1024)
    const float* bv     = (const float*)d_in[8];  // (1024)
    float* out          = (float*)d_out;          // (2048, 1024)

    float *q, *scores, *hidden;
    cudaGetSymbolAddress((void**)&q, g_q);
    cudaGetSymbolAddress((void**)&scores, g_scores);
    cudaGetSymbolAddress((void**)&hidden, g_hidden);
    float* gate;
    cudaGetSymbolAddress((void**)&gate, g_gate);

    // 1) q = x @ Wq + bq           (2048 x 2048, K=1024)
    gemm_k<false, 0><<<dim3(2048 / 64, 2048 / 128, 1), 256>>>(
        x, Wq, bq, q, 1024, 1024, 2048, 2048, 0, 0, 0);

    // 2) scores[n, ht, :] = q[n, ht*256:+256] @ keys[ht]^T   (8 batches, K=256)
    gemm_k<true, 0><<<dim3(512 / 64, 2048 / 128, 8), 256>>>(
        q, keys, nullptr, scores, 256, 2048, 256, 4096,
        256L, 512L * 256L, 512L);

    // 3) stage-1 top-32 per (n, head, half)
    topk1_kernel<<<2048, 256>>>();

    // 4) stage-2 pairwise top-32 + softmax per (n, head)
    topk2_kernel<<<2048, 128>>>();

    // 5) gate = silu(x @ Ws + bs)   (2048 x 512, K=1024)
    gemm_k<false, 1><<<dim3(512 / 64, 2048 / 128, 1), 256>>>(
        x, Ws, bs, gate, 1024, 1024, 512, 512, 0, 0, 0);

    // 6) hidden = gate * sum_k w_k values[idx_k]
    gather_kernel<<<2048, 128>>>(values);

    // 7) out = hidden @ Wv + bv    (2048 x 1024, K=512)
    gemm_k<false, 0><<<dim3(1024 / 64, 2048 / 128, 1), 256>>>(
        hidden, Wv, bv, out, 512, 512, 1024, 1024, 0, 0, 0);
}